// round 7
// baseline (speedup 1.0000x reference)
#include <cuda_runtime.h>

#define NN   8192
#define DIM  128
#define EE   262144
#define CAP  96          // per-node bucket capacity; P(deg>=96) ~ e^-41 per node

// ---------------- scratch (static device globals — no allocation) ----------
// g_cnt relies on zero-init at module load; k_spmm2 re-zeros each row after
// its final use, so every full call sequence starts from the same state.
__device__ int   g_cnt[NN];
__device__ int   g_col[NN * CAP]; // neighbor v per slot
__device__ float g_s[NN];         // deg^{-1/2} (0 if deg==0)
__device__ float g_Z1[NN * DIM];  // L @ x   = x - A_hat x
__device__ float g_Z2[NN * DIM];  // T2 @ x  = 2 L Z1 - x

// ---------------- build: one pass, fixed-slot buckets ----------------------
__global__ void k_fill(const int* __restrict__ ei) {
    int e = blockIdx.x * blockDim.x + threadIdx.x;
    if (e < EE) {
        int u = ei[e] & (NN - 1);          // defensive mask; indices in [0,NN)
        int v = ei[EE + e] & (NN - 1);
        int pos = atomicAdd(&g_cnt[u], 1);
        if (pos < CAP) g_col[u * CAP + pos] = v;   // clamp: no OOB ever
    }
}

__global__ void k_s() {
    int u = blockIdx.x * blockDim.x + threadIdx.x;
    if (u < NN) {
        int d = g_cnt[u];
        g_s[u] = (d > 0) ? rsqrtf((float)d) : 0.0f;
    }
}

// ---------------- SpMM: warp per row, float4 per lane, pipelined MLP-8 -----
__device__ __forceinline__ void acc4(float4& acc, float w, float4 a) {
    acc.x = fmaf(w, a.x, acc.x); acc.y = fmaf(w, a.y, acc.y);
    acc.z = fmaf(w, a.z, acc.z); acc.w = fmaf(w, a.w, acc.w);
}

__device__ __forceinline__ void gather8(float4& acc, const float* __restrict__ X,
                                        int4 ca, int4 cb, int c4) {
    // 8 independent gathers in flight
    float4 a0 = __ldg((const float4*)&X[(ca.x << 7) + c4]);
    float4 a1 = __ldg((const float4*)&X[(ca.y << 7) + c4]);
    float4 a2 = __ldg((const float4*)&X[(ca.z << 7) + c4]);
    float4 a3 = __ldg((const float4*)&X[(ca.w << 7) + c4]);
    float4 a4 = __ldg((const float4*)&X[(cb.x << 7) + c4]);
    float4 a5 = __ldg((const float4*)&X[(cb.y << 7) + c4]);
    float4 a6 = __ldg((const float4*)&X[(cb.z << 7) + c4]);
    float4 a7 = __ldg((const float4*)&X[(cb.w << 7) + c4]);
    // weights hit L1 (32 KB table), off the critical path
    acc4(acc, __ldg(&g_s[ca.x]), a0);
    acc4(acc, __ldg(&g_s[ca.y]), a1);
    acc4(acc, __ldg(&g_s[ca.z]), a2);
    acc4(acc, __ldg(&g_s[ca.w]), a3);
    acc4(acc, __ldg(&g_s[cb.x]), a4);
    acc4(acc, __ldg(&g_s[cb.y]), a5);
    acc4(acc, __ldg(&g_s[cb.z]), a6);
    acc4(acc, __ldg(&g_s[cb.w]), a7);
}

// acc[lane*4..+4) = sum_e s[v_e] * X[v_e, lane*4..+4)
// Column loads for iteration i+1 are prefetched before the gathers of
// iteration i are consumed, hiding the col->gather two-hop latency.
__device__ __forceinline__ float4 spmm_acc_w(const float* __restrict__ X,
                                             const int* __restrict__ cols,
                                             int n, int lane) {
    float4 acc = make_float4(0.f, 0.f, 0.f, 0.f);
    int c4 = lane * 4;
    int e = 0;
    if (n >= 8) {
        int4 ca = __ldg((const int4*)&cols[0]);
        int4 cb = __ldg((const int4*)&cols[4]);
        for (; e + 16 <= n; e += 8) {
            int4 na = __ldg((const int4*)&cols[e + 8]);   // prefetch next chunk
            int4 nb = __ldg((const int4*)&cols[e + 12]);
            gather8(acc, X, ca, cb, c4);
            ca = na; cb = nb;
        }
        gather8(acc, X, ca, cb, c4);                       // last full chunk
        e += 8;
    }
    for (; e < n; e++) {
        int v = __ldg(&cols[e]);
        float4 a = __ldg((const float4*)&X[(v << 7) + c4]);
        acc4(acc, __ldg(&g_s[v]), a);
    }
    return acc;
}

// Z1 = L x = x - s_u * (A_hat-gather of x)
__global__ __launch_bounds__(128) void k_spmm1(const float* __restrict__ x) {
    int u    = blockIdx.x * 4 + (threadIdx.x >> 5);
    int lane = threadIdx.x & 31;
    int n    = min(g_cnt[u], CAP);
    int idx  = u * DIM + lane * 4;
    float4 xv = __ldg((const float4*)&x[idx]);   // overlap with gathers
    float s = g_s[u];
    float4 acc = spmm_acc_w(x, &g_col[u * CAP], n, lane);
    float4 z;
    z.x = xv.x - s * acc.x;
    z.y = xv.y - s * acc.y;
    z.z = xv.z - s * acc.z;
    z.w = xv.w - s * acc.w;
    *(float4*)&g_Z1[idx] = z;
}

// Z2 = 2 L Z1 - x = 2*Z1 - 2*s_u*acc(Z1) - x ; also resets cnt[u] for replay
__global__ __launch_bounds__(128) void k_spmm2(const float* __restrict__ x) {
    int u    = blockIdx.x * 4 + (threadIdx.x >> 5);
    int lane = threadIdx.x & 31;
    int n    = min(g_cnt[u], CAP);
    if (lane == 0) g_cnt[u] = 0;   // last reader of cnt[u]; reset for next call
    int idx = u * DIM + lane * 4;
    float4 xv = __ldg((const float4*)&x[idx]);     // overlap with gathers
    float4 z1 = __ldg((const float4*)&g_Z1[idx]);
    float s2 = 2.0f * g_s[u];
    float4 acc = spmm_acc_w(g_Z1, &g_col[u * CAP], n, lane);
    float4 z;
    z.x = 2.0f * z1.x - s2 * acc.x - xv.x;
    z.y = 2.0f * z1.y - s2 * acc.y - xv.y;
    z.z = 2.0f * z1.z - s2 * acc.z - xv.z;
    z.w = 2.0f * z1.w - s2 * acc.w - xv.w;
    *(float4*)&g_Z2[idx] = z;
}

// ---------------- GEMM: out = [x|Z1|Z2](8192x384) @ W(384x128) + bias ------
// BM=64, BN=128, BK=32, 256 threads, TM=8 x TN=4 microtile per thread.
__global__ __launch_bounds__(256) void k_gemm(const float* __restrict__ x,
                                              const float* __restrict__ wts,
                                              const float* __restrict__ bias,
                                              float* __restrict__ out) {
    __shared__ float As[32][65];    // [k][m], padded
    __shared__ float Bs[32][128];   // [k][n]

    int t    = threadIdx.x;
    int tidn = t & 31;              // 0..31 (n direction, x4)
    int tidm = t >> 5;              // 0..7  (m direction, x8)
    int m0   = blockIdx.x * 64;

    float acc[8][4] = {};

    for (int kt = 0; kt < 384; kt += 32) {
        const float* A = (kt < 128) ? x : (kt < 256 ? g_Z1 : g_Z2);
        int ko = kt & 127;

        // load A tile 64x32 (transposed into As)
#pragma unroll
        for (int p = 0; p < 2; p++) {
            int row = (t >> 3) + p * 32;
            int kb  = (t & 7) * 4;
            float4 v = __ldg((const float4*)&A[(m0 + row) * DIM + ko + kb]);
            As[kb + 0][row] = v.x;
            As[kb + 1][row] = v.y;
            As[kb + 2][row] = v.z;
            As[kb + 3][row] = v.w;
        }
        // load B tile 32x128 (weights for this k-range, row-major)
#pragma unroll
        for (int p = 0; p < 4; p++) {
            int idx = t + p * 256;        // float4 index, 1024 total
            int kk  = idx >> 5;
            int cb  = (idx & 31) * 4;
            *(float4*)&Bs[kk][cb] = __ldg((const float4*)&wts[(kt + kk) * DIM + cb]);
        }
        __syncthreads();

#pragma unroll
        for (int kk = 0; kk < 32; kk++) {
            float a[8], b[4];
#pragma unroll
            for (int i = 0; i < 8; i++) a[i] = As[kk][tidm * 8 + i];
#pragma unroll
            for (int j = 0; j < 4; j++) b[j] = Bs[kk][tidn * 4 + j];
#pragma unroll
            for (int i = 0; i < 8; i++)
#pragma unroll
                for (int j = 0; j < 4; j++)
                    acc[i][j] = fmaf(a[i], b[j], acc[i][j]);
        }
        __syncthreads();
    }

#pragma unroll
    for (int i = 0; i < 8; i++) {
        int r = m0 + tidm * 8 + i;
#pragma unroll
        for (int j = 0; j < 4; j++) {
            int c = tidn * 4 + j;
            out[r * DIM + c] = acc[i][j] + bias[c];
        }
    }
}

// ---------------- launcher --------------------------------------------------
extern "C" void kernel_launch(void* const* d_in, const int* in_sizes, int n_in,
                              void* d_out, int out_size) {
    const float* x    = (const float*)d_in[0];
    const int*   ei   = (const int*)d_in[1];      // int32 (JAX x64 disabled)
    const float* wts  = (const float*)d_in[2];
    const float* bias = (const float*)d_in[3];
    float*       out  = (float*)d_out;

    k_fill<<<EE / 256, 256>>>(ei);
    k_s<<<NN / 256, 256>>>();
    k_spmm1<<<NN / 4, 128>>>(x);
    k_spmm2<<<NN / 4, 128>>>(x);
    k_gemm<<<NN / 64, 256>>>(x, wts, bias, out);
}

// round 8
// speedup vs baseline: 1.0767x; 1.0767x over previous
#include <cuda_runtime.h>

#define NN   8192
#define DIM  128
#define EE   262144
#define CAP  96          // per-node bucket capacity; P(deg>=96) ~ e^-41 per node

// ---------------- scratch (static device globals — no allocation) ----------
// g_cnt relies on zero-init at module load; k_spmm2 re-zeros each row after
// its final use, so every full call sequence starts from the same state.
__device__ int   g_cnt[NN];
__device__ int   g_col[NN * CAP]; // neighbor v per slot
__device__ float g_s[NN];         // deg^{-1/2} (0 if deg==0)
__device__ float g_Z1[NN * DIM];  // L @ x   = x - A_hat x
__device__ float g_Z2[NN * DIM];  // T2 @ x  = 2 L Z1 - x

// ---------------- build: one pass, fixed-slot buckets ----------------------
__global__ void k_fill(const int* __restrict__ ei) {
    int e = blockIdx.x * blockDim.x + threadIdx.x;
    if (e < EE) {
        int u = ei[e] & (NN - 1);          // defensive mask; indices in [0,NN)
        int v = ei[EE + e] & (NN - 1);
        int pos = atomicAdd(&g_cnt[u], 1);
        if (pos < CAP) g_col[u * CAP + pos] = v;   // clamp: no OOB ever
    }
}

__global__ void k_s() {
    int u = blockIdx.x * blockDim.x + threadIdx.x;
    if (u < NN) {
        int d = g_cnt[u];
        g_s[u] = (d > 0) ? rsqrtf((float)d) : 0.0f;
    }
}

// ---------------- SpMM: 2 warps per row, float4 per lane, MLP-8 ------------
__device__ __forceinline__ void acc4(float4& acc, float w, float4 a) {
    acc.x = fmaf(w, a.x, acc.x); acc.y = fmaf(w, a.y, acc.y);
    acc.z = fmaf(w, a.z, acc.z); acc.w = fmaf(w, a.w, acc.w);
}

__device__ __forceinline__ void gather8(float4& acc, const float* __restrict__ X,
                                        int4 ca, int4 cb, int c4) {
    // 8 independent gathers in flight
    float4 a0 = __ldg((const float4*)&X[(ca.x << 7) + c4]);
    float4 a1 = __ldg((const float4*)&X[(ca.y << 7) + c4]);
    float4 a2 = __ldg((const float4*)&X[(ca.z << 7) + c4]);
    float4 a3 = __ldg((const float4*)&X[(ca.w << 7) + c4]);
    float4 a4 = __ldg((const float4*)&X[(cb.x << 7) + c4]);
    float4 a5 = __ldg((const float4*)&X[(cb.y << 7) + c4]);
    float4 a6 = __ldg((const float4*)&X[(cb.z << 7) + c4]);
    float4 a7 = __ldg((const float4*)&X[(cb.w << 7) + c4]);
    // weights hit L1 (32 KB table), off the critical path
    acc4(acc, __ldg(&g_s[ca.x]), a0);
    acc4(acc, __ldg(&g_s[ca.y]), a1);
    acc4(acc, __ldg(&g_s[ca.z]), a2);
    acc4(acc, __ldg(&g_s[ca.w]), a3);
    acc4(acc, __ldg(&g_s[cb.x]), a4);
    acc4(acc, __ldg(&g_s[cb.y]), a5);
    acc4(acc, __ldg(&g_s[cb.z]), a6);
    acc4(acc, __ldg(&g_s[cb.w]), a7);
}

// Partial sum over this warp-half's chunks: half h takes 8-edge chunks with
// chunk parity h; the tail (<8 edges) goes to the half matching the parity of
// the full-chunk count, balancing work.
__device__ __forceinline__ float4 spmm_acc_half(const float* __restrict__ X,
                                                const int* __restrict__ cols,
                                                int n, int lane, int h) {
    float4 acc = make_float4(0.f, 0.f, 0.f, 0.f);
    int c4 = lane * 4;
    int nc = n >> 3;                         // number of full 8-chunks
    for (int c = h; c < nc; c += 2) {
        int4 ca = __ldg((const int4*)&cols[c * 8]);
        int4 cb = __ldg((const int4*)&cols[c * 8 + 4]);
        gather8(acc, X, ca, cb, c4);
    }
    if (h == (nc & 1)) {
        for (int e = nc * 8; e < n; e++) {
            int v = __ldg(&cols[e]);
            float4 a = __ldg((const float4*)&X[(v << 7) + c4]);
            acc4(acc, __ldg(&g_s[v]), a);
        }
    }
    return acc;
}

// Block: 256 threads = 8 warps = 4 rows x 2 half-warps.
// Z1 = L x = x - s_u * (A_hat-gather of x)
__global__ __launch_bounds__(256) void k_spmm1(const float* __restrict__ x) {
    __shared__ float4 part[4][32];
    int wid  = threadIdx.x >> 5;         // 0..7
    int lane = threadIdx.x & 31;
    int r    = wid >> 1;                 // row within block 0..3
    int h    = wid & 1;                  // half 0/1
    int u    = blockIdx.x * 4 + r;
    int n    = min(g_cnt[u], CAP);

    float4 acc = spmm_acc_half(x, &g_col[u * CAP], n, lane, h);

    if (h == 1) part[r][lane] = acc;
    __syncthreads();
    if (h == 0) {
        float4 p = part[r][lane];
        float s  = g_s[u];
        int idx  = u * DIM + lane * 4;
        float4 xv = __ldg((const float4*)&x[idx]);
        float4 z;
        z.x = xv.x - s * (acc.x + p.x);
        z.y = xv.y - s * (acc.y + p.y);
        z.z = xv.z - s * (acc.z + p.z);
        z.w = xv.w - s * (acc.w + p.w);
        *(float4*)&g_Z1[idx] = z;
    }
}

// Z2 = 2 L Z1 - x = 2*Z1 - 2*s_u*acc(Z1) - x ; also resets cnt[u] for replay
__global__ __launch_bounds__(256) void k_spmm2(const float* __restrict__ x) {
    __shared__ float4 part[4][32];
    int wid  = threadIdx.x >> 5;
    int lane = threadIdx.x & 31;
    int r    = wid >> 1;
    int h    = wid & 1;
    int u    = blockIdx.x * 4 + r;
    int n    = min(g_cnt[u], CAP);

    float4 acc = spmm_acc_half(g_Z1, &g_col[u * CAP], n, lane, h);

    if (h == 1) part[r][lane] = acc;
    __syncthreads();                     // also orders cnt read before reset
    if (h == 0) {
        if (lane == 0) g_cnt[u] = 0;     // last reader; reset for next call
        float4 p  = part[r][lane];
        float  s2 = 2.0f * g_s[u];
        int idx   = u * DIM + lane * 4;
        float4 xv = __ldg((const float4*)&x[idx]);
        float4 z1 = __ldg((const float4*)&g_Z1[idx]);
        float4 z;
        z.x = 2.0f * z1.x - s2 * (acc.x + p.x) - xv.x;
        z.y = 2.0f * z1.y - s2 * (acc.y + p.y) - xv.y;
        z.z = 2.0f * z1.z - s2 * (acc.z + p.z) - xv.z;
        z.w = 2.0f * z1.w - s2 * (acc.w + p.w) - xv.w;
        *(float4*)&g_Z2[idx] = z;
    }
}

// ---------------- GEMM: out = [x|Z1|Z2](8192x384) @ W(384x128) + bias ------
// BM=64, BN=128, BK=32, 256 threads, TM=8 x TN=4 microtile per thread.
__global__ __launch_bounds__(256) void k_gemm(const float* __restrict__ x,
                                              const float* __restrict__ wts,
                                              const float* __restrict__ bias,
                                              float* __restrict__ out) {
    __shared__ float As[32][65];    // [k][m], padded
    __shared__ float Bs[32][128];   // [k][n]

    int t    = threadIdx.x;
    int tidn = t & 31;              // 0..31 (n direction, x4)
    int tidm = t >> 5;              // 0..7  (m direction, x8)
    int m0   = blockIdx.x * 64;

    float acc[8][4] = {};

    for (int kt = 0; kt < 384; kt += 32) {
        const float* A = (kt < 128) ? x : (kt < 256 ? g_Z1 : g_Z2);
        int ko = kt & 127;

        // load A tile 64x32 (transposed into As)
#pragma unroll
        for (int p = 0; p < 2; p++) {
            int row = (t >> 3) + p * 32;
            int kb  = (t & 7) * 4;
            float4 v = __ldg((const float4*)&A[(m0 + row) * DIM + ko + kb]);
            As[kb + 0][row] = v.x;
            As[kb + 1][row] = v.y;
            As[kb + 2][row] = v.z;
            As[kb + 3][row] = v.w;
        }
        // load B tile 32x128 (weights for this k-range, row-major)
#pragma unroll
        for (int p = 0; p < 4; p++) {
            int idx = t + p * 256;        // float4 index, 1024 total
            int kk  = idx >> 5;
            int cb  = (idx & 31) * 4;
            *(float4*)&Bs[kk][cb] = __ldg((const float4*)&wts[(kt + kk) * DIM + cb]);
        }
        __syncthreads();

#pragma unroll
        for (int kk = 0; kk < 32; kk++) {
            float a[8], b[4];
#pragma unroll
            for (int i = 0; i < 8; i++) a[i] = As[kk][tidm * 8 + i];
#pragma unroll
            for (int j = 0; j < 4; j++) b[j] = Bs[kk][tidn * 4 + j];
#pragma unroll
            for (int i = 0; i < 8; i++)
#pragma unroll
                for (int j = 0; j < 4; j++)
                    acc[i][j] = fmaf(a[i], b[j], acc[i][j]);
        }
        __syncthreads();
    }

#pragma unroll
    for (int i = 0; i < 8; i++) {
        int r = m0 + tidm * 8 + i;
#pragma unroll
        for (int j = 0; j < 4; j++) {
            int c = tidn * 4 + j;
            out[r * DIM + c] = acc[i][j] + bias[c];
        }
    }
}

// ---------------- launcher --------------------------------------------------
extern "C" void kernel_launch(void* const* d_in, const int* in_sizes, int n_in,
                              void* d_out, int out_size) {
    const float* x    = (const float*)d_in[0];
    const int*   ei   = (const int*)d_in[1];      // int32 (JAX x64 disabled)
    const float* wts  = (const float*)d_in[2];
    const float* bias = (const float*)d_in[3];
    float*       out  = (float*)d_out;

    k_fill<<<EE / 256, 256>>>(ei);
    k_s<<<NN / 256, 256>>>();
    k_spmm1<<<NN / 4, 256>>>(x);
    k_spmm2<<<NN / 4, 256>>>(x);
    k_gemm<<<NN / 64, 256>>>(x, wts, bias, out);
}

// round 9
// speedup vs baseline: 1.1108x; 1.0317x over previous
#include <cuda_runtime.h>
#include <cuda_fp16.h>

#define NN   8192
#define DIM  128
#define EE   262144
#define CAP  96          // per-node bucket capacity; P(deg>=96) ~ e^-41 per node

// ---------------- scratch (static device globals — no allocation) ----------
// g_cnt relies on zero-init at module load; k_spmm2 re-zeros each row after
// its final use, so every full call sequence starts from the same state.
__device__ int    g_cnt[NN];
__device__ int    g_col[NN * CAP];  // neighbor v per slot
__device__ float  g_s[NN];          // deg^{-1/2} (0 if deg==0)
__device__ __align__(16) __half g_xh [NN * DIM]; // fp16 copy of x   (gather operand)
__device__ __align__(16) __half g_Z1h[NN * DIM]; // fp16 copy of Z1  (gather operand)
__device__ float  g_Z1[NN * DIM];   // L @ x   = x - A_hat x   (fp32, for GEMM)
__device__ float  g_Z2[NN * DIM];   // T2 @ x  = 2 L Z1 - x    (fp32, for GEMM)

// ---------------- build: one pass, fixed-slot buckets ----------------------
__global__ void k_fill(const int* __restrict__ ei) {
    int e = blockIdx.x * blockDim.x + threadIdx.x;
    if (e < EE) {
        int u = ei[e] & (NN - 1);          // defensive mask; indices in [0,NN)
        int v = ei[EE + e] & (NN - 1);
        int pos = atomicAdd(&g_cnt[u], 1);
        if (pos < CAP) g_col[u * CAP + pos] = v;   // clamp: no OOB ever
    }
}

// s = rsqrt(deg) for first NN threads; every thread converts 8 floats of x
// to fp16 (NN*DIM/8 = 131072 threads).
__global__ void k_prep(const float* __restrict__ x) {
    int i = blockIdx.x * blockDim.x + threadIdx.x;
    if (i < NN) {
        int d = g_cnt[i];
        g_s[i] = (d > 0) ? rsqrtf((float)d) : 0.0f;
    }
    float4 a = __ldg((const float4*)&x[i * 8]);
    float4 b = __ldg((const float4*)&x[i * 8 + 4]);
    __half2 h0 = __float22half2_rn(make_float2(a.x, a.y));
    __half2 h1 = __float22half2_rn(make_float2(a.z, a.w));
    __half2 h2 = __float22half2_rn(make_float2(b.x, b.y));
    __half2 h3 = __float22half2_rn(make_float2(b.z, b.w));
    uint4 o;
    o.x = *reinterpret_cast<unsigned*>(&h0);
    o.y = *reinterpret_cast<unsigned*>(&h1);
    o.z = *reinterpret_cast<unsigned*>(&h2);
    o.w = *reinterpret_cast<unsigned*>(&h3);
    *(uint4*)&g_xh[i * 8] = o;
}

// ---------------- SpMM: 2 warps per row, fp16 gathers, fp32 accum ----------
__device__ __forceinline__ void acc4(float4& acc, float w, float4 a) {
    acc.x = fmaf(w, a.x, acc.x); acc.y = fmaf(w, a.y, acc.y);
    acc.z = fmaf(w, a.z, acc.z); acc.w = fmaf(w, a.w, acc.w);
}

// load 4 halves at element offset off, widen to float4
__device__ __forceinline__ float4 ldh4(const __half* __restrict__ X, int off) {
    uint2 u = __ldg((const uint2*)(X + off));
    __half2 h0 = *reinterpret_cast<__half2*>(&u.x);
    __half2 h1 = *reinterpret_cast<__half2*>(&u.y);
    float2 f0 = __half22float2(h0);
    float2 f1 = __half22float2(h1);
    return make_float4(f0.x, f0.y, f1.x, f1.y);
}

__device__ __forceinline__ void gather8(float4& acc, const __half* __restrict__ X,
                                        int4 ca, int4 cb, int c4) {
    // 8 independent 8B gathers in flight (256B/edge warp-wide, 2 lines)
    float4 a0 = ldh4(X, (ca.x << 7) + c4);
    float4 a1 = ldh4(X, (ca.y << 7) + c4);
    float4 a2 = ldh4(X, (ca.z << 7) + c4);
    float4 a3 = ldh4(X, (ca.w << 7) + c4);
    float4 a4 = ldh4(X, (cb.x << 7) + c4);
    float4 a5 = ldh4(X, (cb.y << 7) + c4);
    float4 a6 = ldh4(X, (cb.z << 7) + c4);
    float4 a7 = ldh4(X, (cb.w << 7) + c4);
    // weights hit L1 (32 KB table), off the critical path
    acc4(acc, __ldg(&g_s[ca.x]), a0);
    acc4(acc, __ldg(&g_s[ca.y]), a1);
    acc4(acc, __ldg(&g_s[ca.z]), a2);
    acc4(acc, __ldg(&g_s[ca.w]), a3);
    acc4(acc, __ldg(&g_s[cb.x]), a4);
    acc4(acc, __ldg(&g_s[cb.y]), a5);
    acc4(acc, __ldg(&g_s[cb.z]), a6);
    acc4(acc, __ldg(&g_s[cb.w]), a7);
}

// Partial sum over this warp-half's chunks: half h takes 8-edge chunks with
// chunk parity h; the tail (<8 edges) goes to the half matching the parity of
// the full-chunk count, balancing work.
__device__ __forceinline__ float4 spmm_acc_half(const __half* __restrict__ X,
                                                const int* __restrict__ cols,
                                                int n, int lane, int h) {
    float4 acc = make_float4(0.f, 0.f, 0.f, 0.f);
    int c4 = lane * 4;
    int nc = n >> 3;                         // number of full 8-chunks
    for (int c = h; c < nc; c += 2) {
        int4 ca = __ldg((const int4*)&cols[c * 8]);
        int4 cb = __ldg((const int4*)&cols[c * 8 + 4]);
        gather8(acc, X, ca, cb, c4);
    }
    if (h == (nc & 1)) {
        for (int e = nc * 8; e < n; e++) {
            int v = __ldg(&cols[e]);
            acc4(acc, __ldg(&g_s[v]), ldh4(X, (v << 7) + c4));
        }
    }
    return acc;
}

__device__ __forceinline__ uint2 f4_to_h4(float4 z) {
    __half2 h0 = __float22half2_rn(make_float2(z.x, z.y));
    __half2 h1 = __float22half2_rn(make_float2(z.z, z.w));
    uint2 o;
    o.x = *reinterpret_cast<unsigned*>(&h0);
    o.y = *reinterpret_cast<unsigned*>(&h1);
    return o;
}

// Block: 256 threads = 8 warps = 4 rows x 2 half-warps.
// Z1 = L x = x - s_u * (A_hat-gather of x_h) ; stored fp32 + fp16
__global__ __launch_bounds__(256) void k_spmm1(const float* __restrict__ x) {
    __shared__ float4 part[4][32];
    int wid  = threadIdx.x >> 5;         // 0..7
    int lane = threadIdx.x & 31;
    int r    = wid >> 1;                 // row within block 0..3
    int h    = wid & 1;                  // half 0/1
    int u    = blockIdx.x * 4 + r;
    int n    = min(g_cnt[u], CAP);

    float4 acc = spmm_acc_half(g_xh, &g_col[u * CAP], n, lane, h);

    if (h == 1) part[r][lane] = acc;
    __syncthreads();
    if (h == 0) {
        float4 p = part[r][lane];
        float s  = g_s[u];
        int idx  = u * DIM + lane * 4;
        float4 xv = __ldg((const float4*)&x[idx]);
        float4 z;
        z.x = xv.x - s * (acc.x + p.x);
        z.y = xv.y - s * (acc.y + p.y);
        z.z = xv.z - s * (acc.z + p.z);
        z.w = xv.w - s * (acc.w + p.w);
        *(float4*)&g_Z1[idx] = z;
        *(uint2*)&g_Z1h[idx] = f4_to_h4(z);
    }
}

// Z2 = 2 L Z1 - x = 2*Z1 - 2*s_u*acc(Z1h) - x ; also resets cnt[u] for replay
__global__ __launch_bounds__(256) void k_spmm2(const float* __restrict__ x) {
    __shared__ float4 part[4][32];
    int wid  = threadIdx.x >> 5;
    int lane = threadIdx.x & 31;
    int r    = wid >> 1;
    int h    = wid & 1;
    int u    = blockIdx.x * 4 + r;
    int n    = min(g_cnt[u], CAP);

    float4 acc = spmm_acc_half(g_Z1h, &g_col[u * CAP], n, lane, h);

    if (h == 1) part[r][lane] = acc;
    __syncthreads();                     // also orders cnt read before reset
    if (h == 0) {
        if (lane == 0) g_cnt[u] = 0;     // last reader; reset for next call
        float4 p  = part[r][lane];
        float  s2 = 2.0f * g_s[u];
        int idx   = u * DIM + lane * 4;
        float4 xv = __ldg((const float4*)&x[idx]);
        float4 z1 = __ldg((const float4*)&g_Z1[idx]);
        float4 z;
        z.x = 2.0f * z1.x - s2 * (acc.x + p.x) - xv.x;
        z.y = 2.0f * z1.y - s2 * (acc.y + p.y) - xv.y;
        z.z = 2.0f * z1.z - s2 * (acc.z + p.z) - xv.z;
        z.w = 2.0f * z1.w - s2 * (acc.w + p.w) - xv.w;
        *(float4*)&g_Z2[idx] = z;
    }
}

// ---------------- GEMM: out = [x|Z1|Z2](8192x384) @ W(384x128) + bias ------
// BM=64, BN=128, BK=32, 256 threads, TM=8 x TN=4 microtile per thread.
__global__ __launch_bounds__(256) void k_gemm(const float* __restrict__ x,
                                              const float* __restrict__ wts,
                                              const float* __restrict__ bias,
                                              float* __restrict__ out) {
    __shared__ float As[32][65];    // [k][m], padded
    __shared__ float Bs[32][128];   // [k][n]

    int t    = threadIdx.x;
    int tidn = t & 31;              // 0..31 (n direction, x4)
    int tidm = t >> 5;              // 0..7  (m direction, x8)
    int m0   = blockIdx.x * 64;

    float acc[8][4] = {};

    for (int kt = 0; kt < 384; kt += 32) {
        const float* A = (kt < 128) ? x : (kt < 256 ? g_Z1 : g_Z2);
        int ko = kt & 127;

        // load A tile 64x32 (transposed into As)
#pragma unroll
        for (int p = 0; p < 2; p++) {
            int row = (t >> 3) + p * 32;
            int kb  = (t & 7) * 4;
            float4 v = __ldg((const float4*)&A[(m0 + row) * DIM + ko + kb]);
            As[kb + 0][row] = v.x;
            As[kb + 1][row] = v.y;
            As[kb + 2][row] = v.z;
            As[kb + 3][row] = v.w;
        }
        // load B tile 32x128 (weights for this k-range, row-major)
#pragma unroll
        for (int p = 0; p < 4; p++) {
            int idx = t + p * 256;        // float4 index, 1024 total
            int kk  = idx >> 5;
            int cb  = (idx & 31) * 4;
            *(float4*)&Bs[kk][cb] = __ldg((const float4*)&wts[(kt + kk) * DIM + cb]);
        }
        __syncthreads();

#pragma unroll
        for (int kk = 0; kk < 32; kk++) {
            float a[8], b[4];
#pragma unroll
            for (int i = 0; i < 8; i++) a[i] = As[kk][tidm * 8 + i];
#pragma unroll
            for (int j = 0; j < 4; j++) b[j] = Bs[kk][tidn * 4 + j];
#pragma unroll
            for (int i = 0; i < 8; i++)
#pragma unroll
                for (int j = 0; j < 4; j++)
                    acc[i][j] = fmaf(a[i], b[j], acc[i][j]);
        }
        __syncthreads();
    }

#pragma unroll
    for (int i = 0; i < 8; i++) {
        int r = m0 + tidm * 8 + i;
#pragma unroll
        for (int j = 0; j < 4; j++) {
            int c = tidn * 4 + j;
            out[r * DIM + c] = acc[i][j] + bias[c];
        }
    }
}

// ---------------- launcher --------------------------------------------------
extern "C" void kernel_launch(void* const* d_in, const int* in_sizes, int n_in,
                              void* d_out, int out_size) {
    const float* x    = (const float*)d_in[0];
    const int*   ei   = (const int*)d_in[1];      // int32 (JAX x64 disabled)
    const float* wts  = (const float*)d_in[2];
    const float* bias = (const float*)d_in[3];
    float*       out  = (float*)d_out;

    k_fill<<<EE / 256, 256>>>(ei);
    k_prep<<<NN * DIM / 8 / 256, 256>>>(x);
    k_spmm1<<<NN / 4, 256>>>(x);
    k_spmm2<<<NN / 4, 256>>>(x);
    k_gemm<<<NN / 64, 256>>>(x, wts, bias, out);
}

// round 10
// speedup vs baseline: 1.2236x; 1.1016x over previous
#include <cuda_runtime.h>
#include <cuda_fp16.h>

#define NN   8192
#define DIM  128
#define EE   262144
#define CAP  96          // per-node bucket capacity; P(deg>=96) ~ e^-41 per node

// ---------------- scratch (static device globals — no allocation) ----------
// g_cnt relies on zero-init at module load; k_spmm2 re-zeros each row after
// its final use, so every full call sequence starts from the same state.
__device__ int    g_cnt[NN];
__device__ int    g_col[NN * CAP];  // neighbor v per slot
__device__ float  g_s[NN];          // deg^{-1/2} (0 if deg==0)
__device__ __align__(16) __half g_xh [NN * DIM]; // fp16 copy of x   (gather operand)
__device__ __align__(16) __half g_Z1h[NN * DIM]; // fp16 copy of Z1  (gather operand)
__device__ float  g_Z1[NN * DIM];   // L @ x   = x - A_hat x   (fp32, for GEMM)
__device__ float  g_Z2[NN * DIM];   // T2 @ x  = 2 L Z1 - x    (fp32, for GEMM)

// ---------------- build: one pass, fixed-slot buckets ----------------------
__global__ void k_fill(const int* __restrict__ ei) {
    int e = blockIdx.x * blockDim.x + threadIdx.x;
    if (e < EE) {
        int u = ei[e] & (NN - 1);          // defensive mask; indices in [0,NN)
        int v = ei[EE + e] & (NN - 1);
        int pos = atomicAdd(&g_cnt[u], 1);
        if (pos < CAP) g_col[u * CAP + pos] = v;   // clamp: no OOB ever
    }
}

// s = rsqrt(deg) for first NN threads; every thread converts 8 floats of x
// to fp16 (NN*DIM/8 = 131072 threads).
__global__ void k_prep(const float* __restrict__ x) {
    int i = blockIdx.x * blockDim.x + threadIdx.x;
    if (i < NN) {
        int d = g_cnt[i];
        g_s[i] = (d > 0) ? rsqrtf((float)d) : 0.0f;
    }
    float4 a = __ldg((const float4*)&x[i * 8]);
    float4 b = __ldg((const float4*)&x[i * 8 + 4]);
    __half2 h0 = __float22half2_rn(make_float2(a.x, a.y));
    __half2 h1 = __float22half2_rn(make_float2(a.z, a.w));
    __half2 h2 = __float22half2_rn(make_float2(b.x, b.y));
    __half2 h3 = __float22half2_rn(make_float2(b.z, b.w));
    uint4 o;
    o.x = *reinterpret_cast<unsigned*>(&h0);
    o.y = *reinterpret_cast<unsigned*>(&h1);
    o.z = *reinterpret_cast<unsigned*>(&h2);
    o.w = *reinterpret_cast<unsigned*>(&h3);
    *(uint4*)&g_xh[i * 8] = o;
}

// ---------------- SpMM: 2 warps per row, fp16 gathers, fp32 accum ----------
__device__ __forceinline__ void acc4(float4& acc, float w, float4 a) {
    acc.x = fmaf(w, a.x, acc.x); acc.y = fmaf(w, a.y, acc.y);
    acc.z = fmaf(w, a.z, acc.z); acc.w = fmaf(w, a.w, acc.w);
}

// load 4 halves at element offset off, widen to float4
__device__ __forceinline__ float4 ldh4(const __half* __restrict__ X, int off) {
    uint2 u = __ldg((const uint2*)(X + off));
    __half2 h0 = *reinterpret_cast<__half2*>(&u.x);
    __half2 h1 = *reinterpret_cast<__half2*>(&u.y);
    float2 f0 = __half22float2(h0);
    float2 f1 = __half22float2(h1);
    return make_float4(f0.x, f0.y, f1.x, f1.y);
}

__device__ __forceinline__ void gather8(float4& acc, const __half* __restrict__ X,
                                        int4 ca, int4 cb, int c4) {
    // 8 independent 8B gathers in flight
    float4 a0 = ldh4(X, (ca.x << 7) + c4);
    float4 a1 = ldh4(X, (ca.y << 7) + c4);
    float4 a2 = ldh4(X, (ca.z << 7) + c4);
    float4 a3 = ldh4(X, (ca.w << 7) + c4);
    float4 a4 = ldh4(X, (cb.x << 7) + c4);
    float4 a5 = ldh4(X, (cb.y << 7) + c4);
    float4 a6 = ldh4(X, (cb.z << 7) + c4);
    float4 a7 = ldh4(X, (cb.w << 7) + c4);
    acc4(acc, __ldg(&g_s[ca.x]), a0);
    acc4(acc, __ldg(&g_s[ca.y]), a1);
    acc4(acc, __ldg(&g_s[ca.z]), a2);
    acc4(acc, __ldg(&g_s[ca.w]), a3);
    acc4(acc, __ldg(&g_s[cb.x]), a4);
    acc4(acc, __ldg(&g_s[cb.y]), a5);
    acc4(acc, __ldg(&g_s[cb.z]), a6);
    acc4(acc, __ldg(&g_s[cb.w]), a7);
}

// Partial sum over this warp-half's chunks: half h takes 8-edge chunks with
// chunk parity h; the tail goes to the half matching the full-chunk parity.
__device__ __forceinline__ float4 spmm_acc_half(const __half* __restrict__ X,
                                                const int* __restrict__ cols,
                                                int n, int lane, int h) {
    float4 acc = make_float4(0.f, 0.f, 0.f, 0.f);
    int c4 = lane * 4;
    int nc = n >> 3;                         // number of full 8-chunks
    for (int c = h; c < nc; c += 2) {
        int4 ca = __ldg((const int4*)&cols[c * 8]);
        int4 cb = __ldg((const int4*)&cols[c * 8 + 4]);
        gather8(acc, X, ca, cb, c4);
    }
    if (h == (nc & 1)) {
        for (int e = nc * 8; e < n; e++) {
            int v = __ldg(&cols[e]);
            acc4(acc, __ldg(&g_s[v]), ldh4(X, (v << 7) + c4));
        }
    }
    return acc;
}

__device__ __forceinline__ uint2 f4_to_h4(float4 z) {
    __half2 h0 = __float22half2_rn(make_float2(z.x, z.y));
    __half2 h1 = __float22half2_rn(make_float2(z.z, z.w));
    uint2 o;
    o.x = *reinterpret_cast<unsigned*>(&h0);
    o.y = *reinterpret_cast<unsigned*>(&h1);
    return o;
}

// Block: 256 threads = 8 warps = 4 rows x 2 half-warps.
__global__ __launch_bounds__(256) void k_spmm1(const float* __restrict__ x) {
    __shared__ float4 part[4][32];
    int wid  = threadIdx.x >> 5;
    int lane = threadIdx.x & 31;
    int r    = wid >> 1;
    int h    = wid & 1;
    int u    = blockIdx.x * 4 + r;
    int n    = min(g_cnt[u], CAP);

    float4 acc = spmm_acc_half(g_xh, &g_col[u * CAP], n, lane, h);

    if (h == 1) part[r][lane] = acc;
    __syncthreads();
    if (h == 0) {
        float4 p = part[r][lane];
        float s  = g_s[u];
        int idx  = u * DIM + lane * 4;
        float4 xv = __ldg((const float4*)&x[idx]);
        float4 z;
        z.x = xv.x - s * (acc.x + p.x);
        z.y = xv.y - s * (acc.y + p.y);
        z.z = xv.z - s * (acc.z + p.z);
        z.w = xv.w - s * (acc.w + p.w);
        *(float4*)&g_Z1[idx] = z;
        *(uint2*)&g_Z1h[idx] = f4_to_h4(z);
    }
}

__global__ __launch_bounds__(256) void k_spmm2(const float* __restrict__ x) {
    __shared__ float4 part[4][32];
    int wid  = threadIdx.x >> 5;
    int lane = threadIdx.x & 31;
    int r    = wid >> 1;
    int h    = wid & 1;
    int u    = blockIdx.x * 4 + r;
    int n    = min(g_cnt[u], CAP);

    float4 acc = spmm_acc_half(g_Z1h, &g_col[u * CAP], n, lane, h);

    if (h == 1) part[r][lane] = acc;
    __syncthreads();                     // also orders cnt read before reset
    if (h == 0) {
        if (lane == 0) g_cnt[u] = 0;     // last reader; reset for next call
        float4 p  = part[r][lane];
        float  s2 = 2.0f * g_s[u];
        int idx   = u * DIM + lane * 4;
        float4 xv = __ldg((const float4*)&x[idx]);
        float4 z1 = __ldg((const float4*)&g_Z1[idx]);
        float4 z;
        z.x = 2.0f * z1.x - s2 * (acc.x + p.x) - xv.x;
        z.y = 2.0f * z1.y - s2 * (acc.y + p.y) - xv.y;
        z.z = 2.0f * z1.z - s2 * (acc.z + p.z) - xv.z;
        z.w = 2.0f * z1.w - s2 * (acc.w + p.w) - xv.w;
        *(float4*)&g_Z2[idx] = z;
    }
}

// ---------------- GEMM (tf32 tensor cores) ---------------------------------
// out = [x|Z1|Z2](8192x384) @ W(384x128) + bias
// BM=64, BN=128, BK=32; 256 threads = 8 warps in 4(m) x 2(n); warp tile 16x64.
// mma.sync.aligned.m16n8k8.row.col.f32.tf32.tf32.f32

__device__ __forceinline__ float to_tf32(float f) {
    unsigned u;
    asm("cvt.rna.tf32.f32 %0, %1;" : "=r"(u) : "f"(f));
    return __uint_as_float(u);
}

__device__ __forceinline__ void mma_tf32(float4& d,
                                         unsigned a0, unsigned a1,
                                         unsigned a2, unsigned a3,
                                         unsigned b0, unsigned b1) {
    asm volatile(
        "mma.sync.aligned.m16n8k8.row.col.f32.tf32.tf32.f32 "
        "{%0,%1,%2,%3}, {%4,%5,%6,%7}, {%8,%9}, {%0,%1,%2,%3};"
        : "+f"(d.x), "+f"(d.y), "+f"(d.z), "+f"(d.w)
        : "r"(a0), "r"(a1), "r"(a2), "r"(a3), "r"(b0), "r"(b1));
}

__global__ __launch_bounds__(256) void k_gemm(const float* __restrict__ x,
                                              const float* __restrict__ wts,
                                              const float* __restrict__ bias,
                                              float* __restrict__ out) {
    __shared__ float As[32][68];    // [k][m], padded (68*4B: 16B-aligned rows)
    __shared__ float Bs[32][132];   // [k][n], padded (132%32=4 -> conflict-free frags)

    int t      = threadIdx.x;
    int wid    = t >> 5;
    int lane   = t & 31;
    int g      = lane >> 2;         // group 0..7
    int q      = lane & 3;          // quad-lane 0..3
    int warp_m = (wid >> 1) * 16;   // 0,16,32,48
    int warp_n = (wid & 1) * 64;    // 0,64
    int m0     = blockIdx.x * 64;

    float4 acc[8];
#pragma unroll
    for (int j = 0; j < 8; j++) acc[j] = make_float4(0.f, 0.f, 0.f, 0.f);

    for (int kt = 0; kt < 384; kt += 32) {
        const float* A = (kt < 128) ? x : (kt < 256 ? g_Z1 : g_Z2);
        int ko = kt & 127;

        // load A tile 64x32 (transposed into As), tf32-rounded
#pragma unroll
        for (int p = 0; p < 2; p++) {
            int row = (t >> 3) + p * 32;
            int kb  = (t & 7) * 4;
            float4 v = __ldg((const float4*)&A[(m0 + row) * DIM + ko + kb]);
            As[kb + 0][row] = to_tf32(v.x);
            As[kb + 1][row] = to_tf32(v.y);
            As[kb + 2][row] = to_tf32(v.z);
            As[kb + 3][row] = to_tf32(v.w);
        }
        // load B tile 32x128, tf32-rounded
#pragma unroll
        for (int p = 0; p < 4; p++) {
            int idx = t + p * 256;        // float4 index, 1024 total
            int kk  = idx >> 5;
            int cb  = (idx & 31) * 4;
            float4 v = __ldg((const float4*)&wts[(kt + kk) * DIM + cb]);
            v.x = to_tf32(v.x); v.y = to_tf32(v.y);
            v.z = to_tf32(v.z); v.w = to_tf32(v.w);
            *(float4*)&Bs[kk][cb] = v;
        }
        __syncthreads();

#pragma unroll
        for (int ks = 0; ks < 4; ks++) {
            int k0 = ks * 8;
            unsigned a0 = __float_as_uint(As[k0 + q    ][warp_m + g    ]);
            unsigned a1 = __float_as_uint(As[k0 + q    ][warp_m + g + 8]);
            unsigned a2 = __float_as_uint(As[k0 + q + 4][warp_m + g    ]);
            unsigned a3 = __float_as_uint(As[k0 + q + 4][warp_m + g + 8]);
#pragma unroll
            for (int j = 0; j < 8; j++) {
                int n0 = warp_n + j * 8;
                unsigned b0 = __float_as_uint(Bs[k0 + q    ][n0 + g]);
                unsigned b1 = __float_as_uint(Bs[k0 + q + 4][n0 + g]);
                mma_tf32(acc[j], a0, a1, a2, a3, b0, b1);
            }
        }
        __syncthreads();
    }

    // epilogue: c0,c1 at row g, cols 2q,2q+1 ; c2,c3 at row g+8
    int r0 = m0 + warp_m + g;
#pragma unroll
    for (int j = 0; j < 8; j++) {
        int c = warp_n + j * 8 + 2 * q;
        float b0 = __ldg(&bias[c]);
        float b1 = __ldg(&bias[c + 1]);
        out[r0 * DIM + c]           = acc[j].x + b0;
        out[r0 * DIM + c + 1]       = acc[j].y + b1;
        out[(r0 + 8) * DIM + c]     = acc[j].z + b0;
        out[(r0 + 8) * DIM + c + 1] = acc[j].w + b1;
    }
}

// ---------------- launcher --------------------------------------------------
extern "C" void kernel_launch(void* const* d_in, const int* in_sizes, int n_in,
                              void* d_out, int out_size) {
    const float* x    = (const float*)d_in[0];
    const int*   ei   = (const int*)d_in[1];      // int32 (JAX x64 disabled)
    const float* wts  = (const float*)d_in[2];
    const float* bias = (const float*)d_in[3];
    float*       out  = (float*)d_out;

    k_fill<<<EE / 256, 256>>>(ei);
    k_prep<<<NN * DIM / 8 / 256, 256>>>(x);
    k_spmm1<<<NN / 4, 256>>>(x);
    k_spmm2<<<NN / 4, 256>>>(x);
    k_gemm<<<NN / 64, 256>>>(x, wts, bias, out);
}

// round 11
// speedup vs baseline: 1.2760x; 1.0428x over previous
#include <cuda_runtime.h>
#include <cuda_fp16.h>

#define NN   8192
#define DIM  128
#define EE   262144
#define CAP  96          // per-node bucket capacity; P(deg>=96) ~ e^-41 per node

// ---------------- scratch (static device globals — no allocation) ----------
// g_cnt relies on zero-init at module load; k_spmm2 re-zeros each row after
// its final use, so every full call sequence starts from the same state.
__device__ int    g_cnt[NN];
__device__ int    g_col[NN * CAP];  // neighbor v per slot
__device__ float  g_s[NN];          // deg^{-1/2} (0 if deg==0)
__device__ __align__(16) __half g_xsh [NN * DIM]; // fp16( s[v] * x[v]  )  gather operand
__device__ __align__(16) __half g_Z1sh[NN * DIM]; // fp16( s[v] * Z1[v] )  gather operand
__device__ float  g_Z1[NN * DIM];   // L @ x   = x - A_hat x   (fp32, for GEMM)
__device__ float  g_Z2[NN * DIM];   // T2 @ x  = 2 L Z1 - x    (fp32, for GEMM)

// ---------------- build: one pass, fixed-slot buckets ----------------------
__global__ void k_fill(const int* __restrict__ ei) {
    int e = blockIdx.x * blockDim.x + threadIdx.x;
    if (e < EE) {
        int u = ei[e] & (NN - 1);          // defensive mask; indices in [0,NN)
        int v = ei[EE + e] & (NN - 1);
        int pos = atomicAdd(&g_cnt[u], 1);
        if (pos < CAP) g_col[u * CAP + pos] = v;   // clamp: no OOB ever
    }
}

// Each thread handles 8 floats of one row (16 threads/row); re-derives
// s = rsqrt(deg) from g_cnt (cheap, L1-hit) and stores the pre-scaled fp16 row.
__global__ void k_prep(const float* __restrict__ x) {
    int i = blockIdx.x * blockDim.x + threadIdx.x;   // NN*DIM/8 threads
    int row = i >> 4;
    int d = __ldg(&g_cnt[row]);
    float s = (d > 0) ? rsqrtf((float)d) : 0.0f;
    if ((i & 15) == 0) g_s[row] = s;                 // one writer per row
    float4 a = __ldg((const float4*)&x[i * 8]);
    float4 b = __ldg((const float4*)&x[i * 8 + 4]);
    __half2 h0 = __float22half2_rn(make_float2(s * a.x, s * a.y));
    __half2 h1 = __float22half2_rn(make_float2(s * a.z, s * a.w));
    __half2 h2 = __float22half2_rn(make_float2(s * b.x, s * b.y));
    __half2 h3 = __float22half2_rn(make_float2(s * b.z, s * b.w));
    uint4 o;
    o.x = *reinterpret_cast<unsigned*>(&h0);
    o.y = *reinterpret_cast<unsigned*>(&h1);
    o.z = *reinterpret_cast<unsigned*>(&h2);
    o.w = *reinterpret_cast<unsigned*>(&h3);
    *(uint4*)&g_xsh[i * 8] = o;
}

// ---------------- SpMM: 2 warps per row, pre-scaled fp16 gathers -----------
__device__ __forceinline__ float4 f4add(float4 a, float4 b) {
    return make_float4(a.x + b.x, a.y + b.y, a.z + b.z, a.w + b.w);
}

// load 4 halves at element offset off, widen to float4
__device__ __forceinline__ float4 ldh4(const __half* __restrict__ X, int off) {
    uint2 u = __ldg((const uint2*)(X + off));
    __half2 h0 = *reinterpret_cast<__half2*>(&u.x);
    __half2 h1 = *reinterpret_cast<__half2*>(&u.y);
    float2 f0 = __half22float2(h0);
    float2 f1 = __half22float2(h1);
    return make_float4(f0.x, f0.y, f1.x, f1.y);
}

// 8 independent 8B gathers in flight; pure summation (rows pre-scaled),
// tree-reduced before touching acc to shorten the dependence chain.
__device__ __forceinline__ void gather8(float4& acc, const __half* __restrict__ X,
                                        int4 ca, int4 cb, int c4) {
    float4 a0 = ldh4(X, (ca.x << 7) + c4);
    float4 a1 = ldh4(X, (ca.y << 7) + c4);
    float4 a2 = ldh4(X, (ca.z << 7) + c4);
    float4 a3 = ldh4(X, (ca.w << 7) + c4);
    float4 a4 = ldh4(X, (cb.x << 7) + c4);
    float4 a5 = ldh4(X, (cb.y << 7) + c4);
    float4 a6 = ldh4(X, (cb.z << 7) + c4);
    float4 a7 = ldh4(X, (cb.w << 7) + c4);
    float4 s01 = f4add(a0, a1), s23 = f4add(a2, a3);
    float4 s45 = f4add(a4, a5), s67 = f4add(a6, a7);
    acc = f4add(acc, f4add(f4add(s01, s23), f4add(s45, s67)));
}

// Partial sum over this warp-half's chunks: half h takes 8-edge chunks with
// chunk parity h; the tail goes to the half matching the full-chunk parity.
__device__ __forceinline__ float4 spmm_acc_half(const __half* __restrict__ X,
                                                const int* __restrict__ cols,
                                                int n, int lane, int h) {
    float4 acc = make_float4(0.f, 0.f, 0.f, 0.f);
    int c4 = lane * 4;
    int nc = n >> 3;                         // number of full 8-chunks
    for (int c = h; c < nc; c += 2) {
        int4 ca = __ldg((const int4*)&cols[c * 8]);
        int4 cb = __ldg((const int4*)&cols[c * 8 + 4]);
        gather8(acc, X, ca, cb, c4);
    }
    if (h == (nc & 1)) {
        for (int e = nc * 8; e < n; e++) {
            int v = __ldg(&cols[e]);
            acc = f4add(acc, ldh4(X, (v << 7) + c4));
        }
    }
    return acc;
}

__device__ __forceinline__ uint2 f4_to_h4(float4 z) {
    __half2 h0 = __float22half2_rn(make_float2(z.x, z.y));
    __half2 h1 = __float22half2_rn(make_float2(z.z, z.w));
    uint2 o;
    o.x = *reinterpret_cast<unsigned*>(&h0);
    o.y = *reinterpret_cast<unsigned*>(&h1);
    return o;
}

// Block: 256 threads = 8 warps = 4 rows x 2 half-warps.
// Z1 = x - s_u * sum(xs_h) ; also store Z1s_h = fp16(s_u * Z1) for spmm2.
__global__ __launch_bounds__(256) void k_spmm1(const float* __restrict__ x) {
    __shared__ float4 part[4][32];
    int wid  = threadIdx.x >> 5;
    int lane = threadIdx.x & 31;
    int r    = wid >> 1;
    int h    = wid & 1;
    int u    = blockIdx.x * 4 + r;
    int n    = min(g_cnt[u], CAP);

    float4 acc = spmm_acc_half(g_xsh, &g_col[u * CAP], n, lane, h);

    if (h == 1) part[r][lane] = acc;
    __syncthreads();
    if (h == 0) {
        float4 p = part[r][lane];
        float s  = g_s[u];
        int idx  = u * DIM + lane * 4;
        float4 xv = __ldg((const float4*)&x[idx]);
        float4 z;
        z.x = xv.x - s * (acc.x + p.x);
        z.y = xv.y - s * (acc.y + p.y);
        z.z = xv.z - s * (acc.z + p.z);
        z.w = xv.w - s * (acc.w + p.w);
        *(float4*)&g_Z1[idx] = z;
        float4 zs = make_float4(s * z.x, s * z.y, s * z.z, s * z.w);
        *(uint2*)&g_Z1sh[idx] = f4_to_h4(zs);
    }
}

// Z2 = 2*Z1 - 2*s_u*sum(Z1s_h) - x ; also resets cnt[u] for replay
__global__ __launch_bounds__(256) void k_spmm2(const float* __restrict__ x) {
    __shared__ float4 part[4][32];
    int wid  = threadIdx.x >> 5;
    int lane = threadIdx.x & 31;
    int r    = wid >> 1;
    int h    = wid & 1;
    int u    = blockIdx.x * 4 + r;
    int n    = min(g_cnt[u], CAP);

    float4 acc = spmm_acc_half(g_Z1sh, &g_col[u * CAP], n, lane, h);

    if (h == 1) part[r][lane] = acc;
    __syncthreads();                     // also orders cnt read before reset
    if (h == 0) {
        if (lane == 0) g_cnt[u] = 0;     // last reader; reset for next call
        float4 p  = part[r][lane];
        float  s2 = 2.0f * g_s[u];
        int idx   = u * DIM + lane * 4;
        float4 xv = __ldg((const float4*)&x[idx]);
        float4 z1 = __ldg((const float4*)&g_Z1[idx]);
        float4 z;
        z.x = 2.0f * z1.x - s2 * (acc.x + p.x) - xv.x;
        z.y = 2.0f * z1.y - s2 * (acc.y + p.y) - xv.y;
        z.z = 2.0f * z1.z - s2 * (acc.z + p.z) - xv.z;
        z.w = 2.0f * z1.w - s2 * (acc.w + p.w) - xv.w;
        *(float4*)&g_Z2[idx] = z;
    }
}

// ---------------- GEMM (tf32 tensor cores) ---------------------------------
// out = [x|Z1|Z2](8192x384) @ W(384x128) + bias
// BM=64, BN=128, BK=32; 256 threads = 8 warps in 4(m) x 2(n); warp tile 16x64.

__device__ __forceinline__ float to_tf32(float f) {
    unsigned u;
    asm("cvt.rna.tf32.f32 %0, %1;" : "=r"(u) : "f"(f));
    return __uint_as_float(u);
}

__device__ __forceinline__ void mma_tf32(float4& d,
                                         unsigned a0, unsigned a1,
                                         unsigned a2, unsigned a3,
                                         unsigned b0, unsigned b1) {
    asm volatile(
        "mma.sync.aligned.m16n8k8.row.col.f32.tf32.tf32.f32 "
        "{%0,%1,%2,%3}, {%4,%5,%6,%7}, {%8,%9}, {%0,%1,%2,%3};"
        : "+f"(d.x), "+f"(d.y), "+f"(d.z), "+f"(d.w)
        : "r"(a0), "r"(a1), "r"(a2), "r"(a3), "r"(b0), "r"(b1));
}

__global__ __launch_bounds__(256) void k_gemm(const float* __restrict__ x,
                                              const float* __restrict__ wts,
                                              const float* __restrict__ bias,
                                              float* __restrict__ out) {
    __shared__ float As[32][68];    // [k][m], padded
    __shared__ float Bs[32][132];   // [k][n], padded

    int t      = threadIdx.x;
    int wid    = t >> 5;
    int lane   = t & 31;
    int g      = lane >> 2;         // group 0..7
    int q      = lane & 3;          // quad-lane 0..3
    int warp_m = (wid >> 1) * 16;   // 0,16,32,48
    int warp_n = (wid & 1) * 64;    // 0,64
    int m0     = blockIdx.x * 64;

    float4 acc[8];
#pragma unroll
    for (int j = 0; j < 8; j++) acc[j] = make_float4(0.f, 0.f, 0.f, 0.f);

    for (int kt = 0; kt < 384; kt += 32) {
        const float* A = (kt < 128) ? x : (kt < 256 ? g_Z1 : g_Z2);
        int ko = kt & 127;

        // load A tile 64x32 (transposed into As), tf32-rounded
#pragma unroll
        for (int p = 0; p < 2; p++) {
            int row = (t >> 3) + p * 32;
            int kb  = (t & 7) * 4;
            float4 v = __ldg((const float4*)&A[(m0 + row) * DIM + ko + kb]);
            As[kb + 0][row] = to_tf32(v.x);
            As[kb + 1][row] = to_tf32(v.y);
            As[kb + 2][row] = to_tf32(v.z);
            As[kb + 3][row] = to_tf32(v.w);
        }
        // load B tile 32x128, tf32-rounded
#pragma unroll
        for (int p = 0; p < 4; p++) {
            int idx = t + p * 256;        // float4 index, 1024 total
            int kk  = idx >> 5;
            int cb  = (idx & 31) * 4;
            float4 v = __ldg((const float4*)&wts[(kt + kk) * DIM + cb]);
            v.x = to_tf32(v.x); v.y = to_tf32(v.y);
            v.z = to_tf32(v.z); v.w = to_tf32(v.w);
            *(float4*)&Bs[kk][cb] = v;
        }
        __syncthreads();

#pragma unroll
        for (int ks = 0; ks < 4; ks++) {
            int k0 = ks * 8;
            unsigned a0 = __float_as_uint(As[k0 + q    ][warp_m + g    ]);
            unsigned a1 = __float_as_uint(As[k0 + q    ][warp_m + g + 8]);
            unsigned a2 = __float_as_uint(As[k0 + q + 4][warp_m + g    ]);
            unsigned a3 = __float_as_uint(As[k0 + q + 4][warp_m + g + 8]);
#pragma unroll
            for (int j = 0; j < 8; j++) {
                int n0 = warp_n + j * 8;
                unsigned b0 = __float_as_uint(Bs[k0 + q    ][n0 + g]);
                unsigned b1 = __float_as_uint(Bs[k0 + q + 4][n0 + g]);
                mma_tf32(acc[j], a0, a1, a2, a3, b0, b1);
            }
        }
        __syncthreads();
    }

    // epilogue: c0,c1 at row g, cols 2q,2q+1 ; c2,c3 at row g+8
    int r0 = m0 + warp_m + g;
#pragma unroll
    for (int j = 0; j < 8; j++) {
        int c = warp_n + j * 8 + 2 * q;
        float b0 = __ldg(&bias[c]);
        float b1 = __ldg(&bias[c + 1]);
        out[r0 * DIM + c]           = acc[j].x + b0;
        out[r0 * DIM + c + 1]       = acc[j].y + b1;
        out[(r0 + 8) * DIM + c]     = acc[j].z + b0;
        out[(r0 + 8) * DIM + c + 1] = acc[j].w + b1;
    }
}

// ---------------- launcher --------------------------------------------------
extern "C" void kernel_launch(void* const* d_in, const int* in_sizes, int n_in,
                              void* d_out, int out_size) {
    const float* x    = (const float*)d_in[0];
    const int*   ei   = (const int*)d_in[1];      // int32 (JAX x64 disabled)
    const float* wts  = (const float*)d_in[2];
    const float* bias = (const float*)d_in[3];
    float*       out  = (float*)d_out;

    k_fill<<<EE / 256, 256>>>(ei);
    k_prep<<<NN * DIM / 8 / 256, 256>>>(x);
    k_spmm1<<<NN / 4, 256>>>(x);
    k_spmm2<<<NN / 4, 256>>>(x);
    k_gemm<<<NN / 64, 256>>>(x, wts, bias, out);
}

// round 12
// speedup vs baseline: 1.3251x; 1.0385x over previous
#include <cuda_runtime.h>
#include <cuda_fp16.h>

#define NN   8192
#define DIM  128
#define EE   262144
#define CAP  96          // per-node bucket capacity; P(deg>=96) ~ e^-41 per node

// ---------------- scratch (static device globals — no allocation) ----------
// g_cnt relies on zero-init at module load; k_spmm2 re-zeros each row after
// its final use, so every full call sequence starts from the same state.
__device__ int    g_cnt[NN];
__device__ int    g_col[NN * CAP];  // neighbor v per slot
__device__ float  g_s[NN];          // deg^{-1/2} (0 if deg==0)
__device__ __align__(16) __half g_xsh [NN * DIM]; // fp16( s[v] * x[v]  )  gather operand
__device__ __align__(16) __half g_Z1sh[NN * DIM]; // fp16( s[v] * Z1[v] )  gather operand
__device__ float  g_Z1[NN * DIM];   // L @ x   = x - A_hat x   (fp32, for GEMM)
__device__ float  g_Z2[NN * DIM];   // T2 @ x  = 2 L Z1 - x    (fp32, for GEMM)

// ---------------- build: one pass, fixed-slot buckets ----------------------
__global__ void k_fill(const int* __restrict__ ei) {
    int e = blockIdx.x * blockDim.x + threadIdx.x;
    if (e < EE) {
        int u = ei[e] & (NN - 1);          // defensive mask; indices in [0,NN)
        int v = ei[EE + e] & (NN - 1);
        int pos = atomicAdd(&g_cnt[u], 1);
        if (pos < CAP) g_col[u * CAP + pos] = v;   // clamp: no OOB ever
    }
}

// Each thread handles 8 floats of one row (16 threads/row); re-derives
// s = rsqrt(deg) from g_cnt (cheap, L1-hit) and stores the pre-scaled fp16 row.
__global__ void k_prep(const float* __restrict__ x) {
    int i = blockIdx.x * blockDim.x + threadIdx.x;   // NN*DIM/8 threads
    int row = i >> 4;
    int d = __ldg(&g_cnt[row]);
    float s = (d > 0) ? rsqrtf((float)d) : 0.0f;
    if ((i & 15) == 0) g_s[row] = s;                 // one writer per row
    float4 a = __ldg((const float4*)&x[i * 8]);
    float4 b = __ldg((const float4*)&x[i * 8 + 4]);
    __half2 h0 = __float22half2_rn(make_float2(s * a.x, s * a.y));
    __half2 h1 = __float22half2_rn(make_float2(s * a.z, s * a.w));
    __half2 h2 = __float22half2_rn(make_float2(s * b.x, s * b.y));
    __half2 h3 = __float22half2_rn(make_float2(s * b.z, s * b.w));
    uint4 o;
    o.x = *reinterpret_cast<unsigned*>(&h0);
    o.y = *reinterpret_cast<unsigned*>(&h1);
    o.z = *reinterpret_cast<unsigned*>(&h2);
    o.w = *reinterpret_cast<unsigned*>(&h3);
    *(uint4*)&g_xsh[i * 8] = o;
}

// ---------------- SpMM: 2 warps per row, fp16 chunk-tree reduction ---------
__device__ __forceinline__ __half2 as_h2(unsigned u) {
    return *reinterpret_cast<__half2*>(&u);
}

// 8 independent 8B gathers; 3-level HADD2 tree inside the chunk (safe: the
// accumulator is scaled by s~0.18 in the epilogue, shrinking fp16 tree error
// to ~1e-4 absolute on O(1) outputs), single widen, 4 fp32 adds per chunk.
__device__ __forceinline__ void gather8(float4& acc, const __half* __restrict__ X,
                                        int4 ca, int4 cb, int c4) {
    uint2 u0 = __ldg((const uint2*)(X + (ca.x << 7) + c4));
    uint2 u1 = __ldg((const uint2*)(X + (ca.y << 7) + c4));
    uint2 u2 = __ldg((const uint2*)(X + (ca.z << 7) + c4));
    uint2 u3 = __ldg((const uint2*)(X + (ca.w << 7) + c4));
    uint2 u4 = __ldg((const uint2*)(X + (cb.x << 7) + c4));
    uint2 u5 = __ldg((const uint2*)(X + (cb.y << 7) + c4));
    uint2 u6 = __ldg((const uint2*)(X + (cb.z << 7) + c4));
    uint2 u7 = __ldg((const uint2*)(X + (cb.w << 7) + c4));
    __half2 lo = __hadd2(
        __hadd2(__hadd2(as_h2(u0.x), as_h2(u1.x)), __hadd2(as_h2(u2.x), as_h2(u3.x))),
        __hadd2(__hadd2(as_h2(u4.x), as_h2(u5.x)), __hadd2(as_h2(u6.x), as_h2(u7.x))));
    __half2 hi = __hadd2(
        __hadd2(__hadd2(as_h2(u0.y), as_h2(u1.y)), __hadd2(as_h2(u2.y), as_h2(u3.y))),
        __hadd2(__hadd2(as_h2(u4.y), as_h2(u5.y)), __hadd2(as_h2(u6.y), as_h2(u7.y))));
    float2 f0 = __half22float2(lo);
    float2 f1 = __half22float2(hi);
    acc.x += f0.x; acc.y += f0.y; acc.z += f1.x; acc.w += f1.y;
}

// load 4 halves at element offset off, widen to float4 (tail path)
__device__ __forceinline__ float4 ldh4(const __half* __restrict__ X, int off) {
    uint2 u = __ldg((const uint2*)(X + off));
    float2 f0 = __half22float2(as_h2(u.x));
    float2 f1 = __half22float2(as_h2(u.y));
    return make_float4(f0.x, f0.y, f1.x, f1.y);
}

// Partial sum over this warp-half's chunks: half h takes 8-edge chunks with
// chunk parity h; the tail goes to the half matching the full-chunk parity.
__device__ __forceinline__ float4 spmm_acc_half(const __half* __restrict__ X,
                                                const int* __restrict__ cols,
                                                int n, int lane, int h) {
    float4 acc = make_float4(0.f, 0.f, 0.f, 0.f);
    int c4 = lane * 4;
    int nc = n >> 3;                         // number of full 8-chunks
    for (int c = h; c < nc; c += 2) {
        int4 ca = __ldg((const int4*)&cols[c * 8]);
        int4 cb = __ldg((const int4*)&cols[c * 8 + 4]);
        gather8(acc, X, ca, cb, c4);
    }
    if (h == (nc & 1)) {
        for (int e = nc * 8; e < n; e++) {
            int v = __ldg(&cols[e]);
            float4 a = ldh4(X, (v << 7) + c4);
            acc.x += a.x; acc.y += a.y; acc.z += a.z; acc.w += a.w;
        }
    }
    return acc;
}

__device__ __forceinline__ uint2 f4_to_h4(float4 z) {
    __half2 h0 = __float22half2_rn(make_float2(z.x, z.y));
    __half2 h1 = __float22half2_rn(make_float2(z.z, z.w));
    uint2 o;
    o.x = *reinterpret_cast<unsigned*>(&h0);
    o.y = *reinterpret_cast<unsigned*>(&h1);
    return o;
}

// Block: 256 threads = 8 warps = 4 rows x 2 half-warps.
// Z1 = x - s_u * sum(xs_h) ; also store Z1s_h = fp16(s_u * Z1) for spmm2.
__global__ __launch_bounds__(256) void k_spmm1(const float* __restrict__ x) {
    __shared__ float4 part[4][32];
    int wid  = threadIdx.x >> 5;
    int lane = threadIdx.x & 31;
    int r    = wid >> 1;
    int h    = wid & 1;
    int u    = blockIdx.x * 4 + r;
    int n    = min(g_cnt[u], CAP);

    float4 acc = spmm_acc_half(g_xsh, &g_col[u * CAP], n, lane, h);

    if (h == 1) part[r][lane] = acc;
    __syncthreads();
    if (h == 0) {
        float4 p = part[r][lane];
        float s  = g_s[u];
        int idx  = u * DIM + lane * 4;
        float4 xv = __ldg((const float4*)&x[idx]);
        float4 z;
        z.x = xv.x - s * (acc.x + p.x);
        z.y = xv.y - s * (acc.y + p.y);
        z.z = xv.z - s * (acc.z + p.z);
        z.w = xv.w - s * (acc.w + p.w);
        *(float4*)&g_Z1[idx] = z;
        float4 zs = make_float4(s * z.x, s * z.y, s * z.z, s * z.w);
        *(uint2*)&g_Z1sh[idx] = f4_to_h4(zs);
    }
}

// Z2 = 2*Z1 - 2*s_u*sum(Z1s_h) - x ; also resets cnt[u] for replay
__global__ __launch_bounds__(256) void k_spmm2(const float* __restrict__ x) {
    __shared__ float4 part[4][32];
    int wid  = threadIdx.x >> 5;
    int lane = threadIdx.x & 31;
    int r    = wid >> 1;
    int h    = wid & 1;
    int u    = blockIdx.x * 4 + r;
    int n    = min(g_cnt[u], CAP);

    float4 acc = spmm_acc_half(g_Z1sh, &g_col[u * CAP], n, lane, h);

    if (h == 1) part[r][lane] = acc;
    __syncthreads();                     // also orders cnt read before reset
    if (h == 0) {
        if (lane == 0) g_cnt[u] = 0;     // last reader; reset for next call
        float4 p  = part[r][lane];
        float  s2 = 2.0f * g_s[u];
        int idx   = u * DIM + lane * 4;
        float4 xv = __ldg((const float4*)&x[idx]);
        float4 z1 = __ldg((const float4*)&g_Z1[idx]);
        float4 z;
        z.x = 2.0f * z1.x - s2 * (acc.x + p.x) - xv.x;
        z.y = 2.0f * z1.y - s2 * (acc.y + p.y) - xv.y;
        z.z = 2.0f * z1.z - s2 * (acc.z + p.z) - xv.z;
        z.w = 2.0f * z1.w - s2 * (acc.w + p.w) - xv.w;
        *(float4*)&g_Z2[idx] = z;
    }
}

// ---------------- GEMM (tf32 tensor cores) ---------------------------------
// out = [x|Z1|Z2](8192x384) @ W(384x128) + bias
// BM=64, BN=128, BK=32; 256 threads = 8 warps in 4(m) x 2(n); warp tile 16x64.

__device__ __forceinline__ float to_tf32(float f) {
    unsigned u;
    asm("cvt.rna.tf32.f32 %0, %1;" : "=r"(u) : "f"(f));
    return __uint_as_float(u);
}

__device__ __forceinline__ void mma_tf32(float4& d,
                                         unsigned a0, unsigned a1,
                                         unsigned a2, unsigned a3,
                                         unsigned b0, unsigned b1) {
    asm volatile(
        "mma.sync.aligned.m16n8k8.row.col.f32.tf32.tf32.f32 "
        "{%0,%1,%2,%3}, {%4,%5,%6,%7}, {%8,%9}, {%0,%1,%2,%3};"
        : "+f"(d.x), "+f"(d.y), "+f"(d.z), "+f"(d.w)
        : "r"(a0), "r"(a1), "r"(a2), "r"(a3), "r"(b0), "r"(b1));
}

__global__ __launch_bounds__(256) void k_gemm(const float* __restrict__ x,
                                              const float* __restrict__ wts,
                                              const float* __restrict__ bias,
                                              float* __restrict__ out) {
    __shared__ float As[32][68];    // [k][m], padded
    __shared__ float Bs[32][132];   // [k][n], padded

    int t      = threadIdx.x;
    int wid    = t >> 5;
    int lane   = t & 31;
    int g      = lane >> 2;         // group 0..7
    int q      = lane & 3;          // quad-lane 0..3
    int warp_m = (wid >> 1) * 16;   // 0,16,32,48
    int warp_n = (wid & 1) * 64;    // 0,64
    int m0     = blockIdx.x * 64;

    float4 acc[8];
#pragma unroll
    for (int j = 0; j < 8; j++) acc[j] = make_float4(0.f, 0.f, 0.f, 0.f);

    for (int kt = 0; kt < 384; kt += 32) {
        const float* A = (kt < 128) ? x : (kt < 256 ? g_Z1 : g_Z2);
        int ko = kt & 127;

        // load A tile 64x32 (transposed into As), tf32-rounded
#pragma unroll
        for (int p = 0; p < 2; p++) {
            int row = (t >> 3) + p * 32;
            int kb  = (t & 7) * 4;
            float4 v = __ldg((const float4*)&A[(m0 + row) * DIM + ko + kb]);
            As[kb + 0][row] = to_tf32(v.x);
            As[kb + 1][row] = to_tf32(v.y);
            As[kb + 2][row] = to_tf32(v.z);
            As[kb + 3][row] = to_tf32(v.w);
        }
        // load B tile 32x128, tf32-rounded
#pragma unroll
        for (int p = 0; p < 4; p++) {
            int idx = t + p * 256;        // float4 index, 1024 total
            int kk  = idx >> 5;
            int cb  = (idx & 31) * 4;
            float4 v = __ldg((const float4*)&wts[(kt + kk) * DIM + cb]);
            v.x = to_tf32(v.x); v.y = to_tf32(v.y);
            v.z = to_tf32(v.z); v.w = to_tf32(v.w);
            *(float4*)&Bs[kk][cb] = v;
        }
        __syncthreads();

#pragma unroll
        for (int ks = 0; ks < 4; ks++) {
            int k0 = ks * 8;
            unsigned a0 = __float_as_uint(As[k0 + q    ][warp_m + g    ]);
            unsigned a1 = __float_as_uint(As[k0 + q    ][warp_m + g + 8]);
            unsigned a2 = __float_as_uint(As[k0 + q + 4][warp_m + g    ]);
            unsigned a3 = __float_as_uint(As[k0 + q + 4][warp_m + g + 8]);
#pragma unroll
            for (int j = 0; j < 8; j++) {
                int n0 = warp_n + j * 8;
                unsigned b0 = __float_as_uint(Bs[k0 + q    ][n0 + g]);
                unsigned b1 = __float_as_uint(Bs[k0 + q + 4][n0 + g]);
                mma_tf32(acc[j], a0, a1, a2, a3, b0, b1);
            }
        }
        __syncthreads();
    }

    // epilogue: c0,c1 at row g, cols 2q,2q+1 ; c2,c3 at row g+8
    int r0 = m0 + warp_m + g;
#pragma unroll
    for (int j = 0; j < 8; j++) {
        int c = warp_n + j * 8 + 2 * q;
        float b0 = __ldg(&bias[c]);
        float b1 = __ldg(&bias[c + 1]);
        out[r0 * DIM + c]           = acc[j].x + b0;
        out[r0 * DIM + c + 1]       = acc[j].y + b1;
        out[(r0 + 8) * DIM + c]     = acc[j].z + b0;
        out[(r0 + 8) * DIM + c + 1] = acc[j].w + b1;
    }
}

// ---------------- launcher --------------------------------------------------
extern "C" void kernel_launch(void* const* d_in, const int* in_sizes, int n_in,
                              void* d_out, int out_size) {
    const float* x    = (const float*)d_in[0];
    const int*   ei   = (const int*)d_in[1];      // int32 (JAX x64 disabled)
    const float* wts  = (const float*)d_in[2];
    const float* bias = (const float*)d_in[3];
    float*       out  = (float*)d_out;

    k_fill<<<EE / 256, 256>>>(ei);
    k_prep<<<NN * DIM / 8 / 256, 256>>>(x);
    k_spmm1<<<NN / 4, 256>>>(x);
    k_spmm2<<<NN / 4, 256>>>(x);
    k_gemm<<<NN / 64, 256>>>(x, wts, bias, out);
}